// round 2
// baseline (speedup 1.0000x reference)
#include <cuda_runtime.h>
#include <cstdint>
#include <math.h>

#define Bsz 64
#define Tsz 4096
#define Dsz 128
#define Hsz 256

// Scratch for the input projection xp = x @ Wx + bx  : [B][T][H] fp32 (268 MB)
__device__ float g_xp[(size_t)Bsz * Tsz * Hsz];

// ---------------- packed fp32x2 helpers (sm_103a) ----------------
__device__ __forceinline__ unsigned long long pack2(float a, float b) {
    unsigned long long r;
    asm("mov.b64 %0, {%1, %2};" : "=l"(r) : "f"(a), "f"(b));
    return r;
}
__device__ __forceinline__ void fma2(unsigned long long& d, unsigned long long a, unsigned long long b) {
    asm("fma.rn.f32x2 %0, %1, %2, %0;" : "+l"(d) : "l"(a), "l"(b));
}
__device__ __forceinline__ unsigned long long add2(unsigned long long a, unsigned long long b) {
    unsigned long long r;
    asm("add.rn.f32x2 %0, %1, %2;" : "=l"(r) : "l"(a), "l"(b));
    return r;
}
__device__ __forceinline__ float2 unpack2(unsigned long long p) {
    float2 v;
    asm("mov.b64 {%0, %1}, %2;" : "=f"(v.x), "=f"(v.y) : "l"(p));
    return v;
}

__device__ __forceinline__ void mbar_wait_parity(unsigned addr, unsigned phase) {
    asm volatile(
        "{\n"
        ".reg .pred P%=;\n"
        "LW%=:\n"
        "mbarrier.try_wait.parity.acquire.cluster.shared::cta.b64 P%=, [%0], %1, 0x989680;\n"
        "@P%= bra LD%=;\n"
        "bra LW%=;\n"
        "LD%=:\n"
        "}\n"
        :: "r"(addr), "r"(phase) : "memory");
}

// =====================================================================
// Kernel 1: xp = x @ Wx + bx
//   x: [B*T, 128], Wx: [128, 256]  ->  g_xp: [B*T, 256]
//   Tile 128(M) x 64(N), K=128 fully resident in smem, FFMA2 microkernel.
// =====================================================================
__global__ void __launch_bounds__(256, 2) xp_gemm_kernel(
    const float* __restrict__ x,
    const float* __restrict__ Wx,
    const float* __restrict__ bx)
{
    extern __shared__ float sm[];
    float* xs = sm;               // [128][128], k-major: xs[k*128 + m]
    float* ws = sm + 128 * 128;   // [128][64] : ws[k*64 + n]

    const int tid = threadIdx.x;
    const size_t row0 = (size_t)blockIdx.x * 128;
    const int n_off = blockIdx.y * 64;

    // Load x tile (transposed into k-major)
    {
        const int row = tid & 127;
        const int kh  = (tid >> 7) * 64;
        const float4* src = (const float4*)(x + (row0 + row) * Dsz + kh);
#pragma unroll
        for (int i = 0; i < 16; ++i) {
            float4 v = src[i];
            int k = kh + i * 4;
            xs[(k + 0) * 128 + row] = v.x;
            xs[(k + 1) * 128 + row] = v.y;
            xs[(k + 2) * 128 + row] = v.z;
            xs[(k + 3) * 128 + row] = v.w;
        }
    }
    // Load W tile
    {
        const int k = tid >> 1;
        const int half = (tid & 1) * 32;
        const float4* src = (const float4*)(Wx + (size_t)k * Hsz + n_off + half);
        float4* dst = (float4*)(ws + k * 64 + half);
#pragma unroll
        for (int i = 0; i < 8; ++i) dst[i] = src[i];
    }
    __syncthreads();

    const int im = tid >> 4, in = tid & 15;
    const int m0 = im * 8, n0 = in * 4;

    unsigned long long acc[4][4];
#pragma unroll
    for (int i = 0; i < 4; ++i)
#pragma unroll
        for (int j = 0; j < 4; ++j) acc[i][j] = 0ULL;

#pragma unroll 8
    for (int k = 0; k < 128; ++k) {
        const ulonglong2* ap = (const ulonglong2*)(xs + k * 128 + m0);
        ulonglong2 av0 = ap[0];
        ulonglong2 av1 = ap[1];
        unsigned long long a[4] = {av0.x, av0.y, av1.x, av1.y};
        float4 bv = *(const float4*)(ws + k * 64 + n0);
        unsigned long long bd[4];
        bd[0] = pack2(bv.x, bv.x);
        bd[1] = pack2(bv.y, bv.y);
        bd[2] = pack2(bv.z, bv.z);
        bd[3] = pack2(bv.w, bv.w);
#pragma unroll
        for (int i = 0; i < 4; ++i)
#pragma unroll
            for (int j = 0; j < 4; ++j)
                fma2(acc[i][j], a[i], bd[j]);
    }

    // Epilogue: + bx, store to g_xp
    float bxv[4];
#pragma unroll
    for (int j = 0; j < 4; ++j) bxv[j] = __ldg(&bx[n_off + n0 + j]);

#pragma unroll
    for (int i = 0; i < 4; ++i) {
        float4 o0, o1;
        float2 c0 = unpack2(acc[i][0]); o0.x = c0.x + bxv[0]; o1.x = c0.y + bxv[0];
        float2 c1 = unpack2(acc[i][1]); o0.y = c1.x + bxv[1]; o1.y = c1.y + bxv[1];
        float2 c2 = unpack2(acc[i][2]); o0.z = c2.x + bxv[2]; o1.z = c2.y + bxv[2];
        float2 c3 = unpack2(acc[i][3]); o0.w = c3.x + bxv[3]; o1.w = c3.y + bxv[3];
        size_t r0 = row0 + m0 + 2 * i;
        *(float4*)(g_xp + r0 * Hsz + n_off + n0)       = o0;
        *(float4*)(g_xp + (r0 + 1) * Hsz + n_off + n0) = o1;
    }
}

// =====================================================================
// Kernel 2: recurrence. 64 clusters x 2 CTAs, 512 threads/CTA.
//   CTA rank r owns output columns [r*128, r*128+128).
//   Thread (q = tid>>7, c = tid&127): k-chunk [64q,64q+64), column r*128+c.
//   Wh chunk lives in 64 registers (32 f32x2 pairs). h exchanged via
//   st.async to peer SMEM + double-buffered mbarriers.
// =====================================================================
__global__ void __cluster_dims__(2, 1, 1) __launch_bounds__(512, 1)
rnn_kernel(const float* __restrict__ Wh,
           const float* __restrict__ bh,
           float* __restrict__ out)
{
    __shared__ __align__(16) float hbuf[2 * Hsz];
    __shared__ float red[3 * 128];
    __shared__ __align__(8) unsigned long long mbar[2];

    const int tid = threadIdx.x;
    const int q = tid >> 7;
    const int c = tid & 127;

    unsigned rank;
    asm("mov.u32 %0, %%cluster_ctarank;" : "=r"(rank));
    const int b = blockIdx.x >> 1;
    const int cg = (int)rank * 128 + c;   // this thread's output column

    // Register-resident Wh chunk: k in [64q, 64q+64), column cg
    unsigned long long w[32];
#pragma unroll
    for (int j = 0; j < 32; ++j) {
        int k = q * 64 + 2 * j;
        w[j] = pack2(__ldg(&Wh[(size_t)k * Hsz + cg]),
                     __ldg(&Wh[(size_t)(k + 1) * Hsz + cg]));
    }

    // Threads whose k-chunk lives in the PEER's half must wait the mbarrier.
    const bool waitp = (rank == 0) ? (q >= 2) : (q < 2);
    const int rearm_tid = (rank == 0) ? 256 : 0;   // a thread that waits

    const unsigned hb_s  = (unsigned)__cvta_generic_to_shared(hbuf);
    const unsigned bar_s = (unsigned)__cvta_generic_to_shared(mbar);
    const unsigned peer = rank ^ 1u;
    unsigned hb_peer, bar_peer;
    asm("mapa.shared::cluster.u32 %0, %1, %2;" : "=r"(hb_peer) : "r"(hb_s), "r"(peer));
    asm("mapa.shared::cluster.u32 %0, %1, %2;" : "=r"(bar_peer) : "r"(bar_s), "r"(peer));

    if (tid < Hsz) hbuf[tid] = 0.0f;  // h_0 = 0 (buffer 0)
    if (tid == 0) {
        asm volatile("mbarrier.init.shared.b64 [%0], 1;" :: "r"(bar_s) : "memory");
        asm volatile("mbarrier.init.shared.b64 [%0], 1;" :: "r"(bar_s + 8) : "memory");
    }
    __syncthreads();
    if (tid == rearm_tid) {  // pre-arm both bars (512 bytes = 128 floats each phase)
        asm volatile("mbarrier.arrive.expect_tx.shared.b64 _, [%0], 512;" :: "r"(bar_s) : "memory");
        asm volatile("mbarrier.arrive.expect_tx.shared.b64 _, [%0], 512;" :: "r"(bar_s + 8) : "memory");
    }
    asm volatile("barrier.cluster.arrive.aligned;" ::: "memory");
    asm volatile("barrier.cluster.wait.aligned;" ::: "memory");

    const bool isq0 = (q == 0);
    float bhv = 0.0f, xpc = 0.0f, xpn = 0.0f;
    const size_t xbase = ((size_t)b * Tsz) * Hsz + cg;
    if (isq0) {
        bhv = __ldg(&bh[cg]);
        xpc = g_xp[xbase];  // xp for t = 0
    }
    unsigned p0 = 0, p1 = 0;

    for (int t = 0; t < Tsz; ++t) {
        if (t > 0) {
            if (t & 1) {
                unsigned bs = bar_s + 8;
                if (waitp) mbar_wait_parity(bs, p1);
                if (tid == rearm_tid)
                    asm volatile("mbarrier.arrive.expect_tx.shared.b64 _, [%0], 512;" :: "r"(bs) : "memory");
                p1 ^= 1u;
            } else {
                unsigned bs = bar_s;
                if (waitp) mbar_wait_parity(bs, p0);
                if (tid == rearm_tid)
                    asm volatile("mbarrier.arrive.expect_tx.shared.b64 _, [%0], 512;" :: "r"(bs) : "memory");
                p0 ^= 1u;
            }
        }
        // Prefetch next step's xp one step ahead (latency hidden behind FFMAs)
        if (isq0 && t + 1 < Tsz) xpn = __ldg(&g_xp[xbase + (size_t)(t + 1) * Hsz]);

        // partial = sum_{k in chunk} h[k] * Wh[k][cg]   (FFMA2, weights in regs)
        const float* hcur = hbuf + (t & 1) * Hsz + q * 64;
        unsigned long long a0 = 0, a1 = 0, a2 = 0, a3 = 0;
#pragma unroll
        for (int j = 0; j < 16; ++j) {
            ulonglong2 hv = ((const ulonglong2*)hcur)[j];
            fma2(((j & 1) ? a2 : a0), hv.x, w[2 * j]);
            fma2(((j & 1) ? a3 : a1), hv.y, w[2 * j + 1]);
        }
        float2 v = unpack2(add2(add2(a0, a1), add2(a2, a3)));
        float partial = v.x + v.y;

        if (q != 0) red[(q - 1) * 128 + c] = partial;
        __syncthreads();

        if (isq0) {
            float s = partial + red[c] + red[128 + c] + red[256 + c] + xpc + bhv;
            float hn = tanhf(s);
            int nb = (t + 1) & 1;
            hbuf[nb * Hsz + cg] = hn;                    // own half, local
            out[xbase + (size_t)t * Hsz] = hn;           // output h_seq[t]
            if (t + 1 < Tsz) {                           // send to peer half
                unsigned dst = hb_peer + (unsigned)(nb * Hsz + cg) * 4u;
                unsigned mb  = bar_peer + (unsigned)nb * 8u;
                asm volatile(
                    "st.async.shared::cluster.mbarrier::complete_tx::bytes.b32 [%0], %1, [%2];"
                    :: "r"(dst), "r"(__float_as_uint(hn)), "r"(mb) : "memory");
            }
            xpc = xpn;
        }
        __syncthreads();
    }

    asm volatile("barrier.cluster.arrive.aligned;" ::: "memory");
    asm volatile("barrier.cluster.wait.aligned;" ::: "memory");
}

// =====================================================================
extern "C" void kernel_launch(void* const* d_in, const int* in_sizes, int n_in,
                              void* d_out, int out_size)
{
    const float* x  = (const float*)d_in[0];  // [64, 4096, 128]
    const float* Wx = (const float*)d_in[1];  // [128, 256]
    const float* bx = (const float*)d_in[2];  // [256]
    const float* Wh = (const float*)d_in[3];  // [256, 256]
    const float* bh = (const float*)d_in[4];  // [256]
    float* out = (float*)d_out;               // [64, 4096, 256]

    const int smem_bytes = (128 * 128 + 128 * 64) * 4;  // 96 KB
    cudaFuncSetAttribute(xp_gemm_kernel,
                         cudaFuncAttributeMaxDynamicSharedMemorySize, smem_bytes);

    dim3 ggrid((Bsz * Tsz) / 128, Hsz / 64, 1);
    xp_gemm_kernel<<<ggrid, 256, smem_bytes>>>(x, Wx, bx);

    rnn_kernel<<<2 * Bsz, 512>>>(Wh, bh, out);
}